// round 4
// baseline (speedup 1.0000x reference)
#include <cuda_runtime.h>
#include <cstdint>

// 3x3 conv s1 p1, implicit GEMM on mma.sync m16n8k8 tf32 (sm_103 baseline PTX).
// R4: inputs pre-converted to tf32 in __device__ scratch (no cvt in hot loop),
// smem layouts repacked so all fragment loads are 64-bit conflict-free LDS.
// x:[256,512,512] f32, W:[3,3,256,256] HWIO, b:[256], out:[256,512,512].

#define HH 512
#define WW 512
#define HWSZ (512*512)
#define C_OUT 256
#define NCHUNK 72
#define RSTRIDE 40                         // floats per row (m- or n-major), conflict-free LDS.64
#define TILE_BYTES (128 * RSTRIDE * 4)     // 20480
#define STAGE_BYTES (2 * TILE_BYTES)       // A + B = 40960
#define SMEM_BYTES (2 * STAGE_BYTES)       // 81920

// tf32 scratch (bss, not allocations)
__device__ uint32_t g_x[256 * HWSZ];
__device__ uint32_t g_w[9 * 256 * 256];    // packed: [k9][cic(8)][coh(2)][n(128)][k32 interleaved]

__device__ __forceinline__ uint32_t to_tf32(float f) {
    uint32_t r;
    asm("cvt.rna.tf32.f32 %0, %1;" : "=r"(r) : "f"(f));
    return r;
}
__device__ __forceinline__ void cp_async4(uint32_t dst, const void* src, uint32_t sz) {
    asm volatile("cp.async.ca.shared.global [%0], [%1], 4, %2;"
                 :: "r"(dst), "l"(src), "r"(sz) : "memory");
}
__device__ __forceinline__ void cp_async16(uint32_t dst, const void* src) {
    asm volatile("cp.async.cg.shared.global [%0], [%1], 16;"
                 :: "r"(dst), "l"(src) : "memory");
}
__device__ __forceinline__ void cp_commit() {
    asm volatile("cp.async.commit_group;" ::: "memory");
}
__device__ __forceinline__ void cp_wait1() {
    asm volatile("cp.async.wait_group 1;" ::: "memory");
}
__device__ __forceinline__ void lds64(uint32_t& a, uint32_t& b, uint32_t addr) {
    asm volatile("ld.shared.v2.b32 {%0,%1}, [%2];" : "=r"(a), "=r"(b) : "r"(addr));
}
__device__ __forceinline__ void mma_tf32(float* c, const uint32_t* a, const uint32_t* b) {
    asm volatile(
        "mma.sync.aligned.m16n8k8.row.col.f32.tf32.tf32.f32 "
        "{%0,%1,%2,%3}, {%4,%5,%6,%7}, {%8,%9}, {%0,%1,%2,%3};"
        : "+f"(c[0]), "+f"(c[1]), "+f"(c[2]), "+f"(c[3])
        : "r"(a[0]), "r"(a[1]), "r"(a[2]), "r"(a[3]), "r"(b[0]), "r"(b[1]));
}

// interleave within a 32-k group so (k, k+4) become adjacent
__device__ __forceinline__ int physk(int k) {
    return (k & 24) + ((k & 3) << 1) + ((k >> 2) & 1);
}

// ---------------- prepasses ----------------
__global__ void prep_x(const float4* __restrict__ x) {
    const int i = blockIdx.x * 256 + threadIdx.x;   // 16777216 float4s
    const float4 v = x[i];
    uint4 o;
    o.x = to_tf32(v.x); o.y = to_tf32(v.y); o.z = to_tf32(v.z); o.w = to_tf32(v.w);
    reinterpret_cast<uint4*>(g_x)[i] = o;
}
__global__ void prep_w(const float* __restrict__ w) {
    const int idx = blockIdx.x * 256 + threadIdx.x;  // 589824
    const int co = idx & 255;
    const int ci = (idx >> 8) & 255;
    const int k9 = idx >> 16;
    const int dst = (((k9 * 8 + (ci >> 5)) * 2 + (co >> 7)) << 12) +
                    ((co & 127) << 5) + physk(ci & 31);
    g_w[dst] = to_tf32(w[idx]);
}

// ---------------- main kernel ----------------
__global__ void __launch_bounds__(256, 2)
conv_mma(const float* __restrict__ bias, float* __restrict__ out)
{
    extern __shared__ uint32_t dsm[];

    const int tid  = threadIdx.x;
    const int wid  = tid >> 5;
    const int lane = tid & 31;
    const int gid  = lane >> 2;     // 0..7
    const int tig  = lane & 3;      // 0..3
    const int wm   = wid & 3;       // warp m-offset: 32*wm
    const int wn   = wid >> 2;      // warp n-offset: 64*wn

    const int w0  = blockIdx.x * 128;
    const int h   = blockIdx.y;
    const int coh = blockIdx.z;     // cout half
    const int co0 = coh * 128;

    const uint32_t sbase = (uint32_t)__cvta_generic_to_shared(dsm);

    float acc[2][8][4];
#pragma unroll
    for (int mt = 0; mt < 2; mt++)
#pragma unroll
        for (int nt = 0; nt < 8; nt++)
#pragma unroll
            for (int i = 0; i < 4; i++)
                acc[mt][nt][i] = 0.f;

    auto load_chunk = [&](int c, int stage) {
        const int kh  = c / 24;
        const int r   = c % 24;
        const int kw  = r >> 3;
        const int cic = r & 7;
        const int ci0 = cic * 32;

        const uint32_t abase = sbase + (uint32_t)stage * STAGE_BYTES;
        const uint32_t bbase = abase + TILE_BYTES;

        const int h2  = h + kh - 1;
        const bool hok = (unsigned)h2 < (unsigned)HH;
        const uint32_t* xrow = g_x + (size_t)ci0 * HWSZ + (size_t)(hok ? h2 : 0) * WW;

        // A: im2col [m=128][k=32 interleaved], 16 scalars/thread
#pragma unroll
        for (int i = 0; i < 16; i++) {
            const int j = tid + i * 256;
            const int k = j >> 7, m = j & 127;
            const int w2 = w0 + m + kw - 1;
            const bool ok = hok && ((unsigned)w2 < (unsigned)WW);
            const uint32_t* src = xrow + (size_t)k * HWSZ + (ok ? w2 : 0);
            cp_async4(abase + (uint32_t)(m * RSTRIDE + physk(k)) * 4u, src, ok ? 4u : 0u);
        }
        // B: pre-packed tile [n=128][k=32 interleaved] -> 4x16B per thread
        const uint32_t* wb = g_w + ((((size_t)(kh * 3 + kw)) * 8 + cic) * 2 + coh) * 4096;
#pragma unroll
        for (int i = 0; i < 4; i++) {
            const int j = tid + i * 256;
            const int n = j >> 3, q = (j & 7) * 4;
            cp_async16(bbase + (uint32_t)(n * RSTRIDE + q) * 4u, wb + n * 32 + q);
        }
    };

    load_chunk(0, 0); cp_commit();
    load_chunk(1, 1); cp_commit();

    // frag base addrs (depend only on lane/warp)
    const uint32_t aoff = (uint32_t)((wm * 32 + gid) * RSTRIDE + tig * 2) * 4u;
    const uint32_t boff = (uint32_t)((wn * 64 + gid) * RSTRIDE + tig * 2) * 4u;

    for (int c = 0; c < NCHUNK; c++) {
        cp_wait1();
        __syncthreads();

        const uint32_t sA = sbase + (uint32_t)(c & 1) * STAGE_BYTES;
        const uint32_t sB = sA + TILE_BYTES;

#pragma unroll
        for (int ks = 0; ks < 4; ks++) {
            const uint32_t kso = (uint32_t)(ks * 8) * 4u;   // 8 floats per ks step
            uint32_t afrag[2][4];
#pragma unroll
            for (int mt = 0; mt < 2; mt++) {
                const uint32_t a0 = sA + aoff + kso + (uint32_t)(mt * 16 * RSTRIDE) * 4u;
                lds64(afrag[mt][0], afrag[mt][2], a0);
                lds64(afrag[mt][1], afrag[mt][3], a0 + (uint32_t)(8 * RSTRIDE) * 4u);
            }
            uint32_t bfrag[8][2];
#pragma unroll
            for (int nt = 0; nt < 8; nt++) {
                lds64(bfrag[nt][0], bfrag[nt][1],
                      sB + boff + kso + (uint32_t)(nt * 8 * RSTRIDE) * 4u);
            }
#pragma unroll
            for (int mt = 0; mt < 2; mt++)
#pragma unroll
                for (int nt = 0; nt < 8; nt++)
                    mma_tf32(acc[mt][nt], afrag[mt], bfrag[nt]);
        }

        __syncthreads();
        if (c + 2 < NCHUNK) load_chunk(c + 2, c & 1);
        cp_commit();
    }

    // ---- epilogue: bias + store ----
    const size_t prow = (size_t)h * WW + w0;
#pragma unroll
    for (int nt = 0; nt < 8; nt++) {
        const int co = co0 + wn * 64 + nt * 8 + tig * 2;
        const float b0 = __ldg(bias + co);
        const float b1 = __ldg(bias + co + 1);
        float* o0 = out + (size_t)co * HWSZ + prow;
        float* o1 = o0 + HWSZ;
#pragma unroll
        for (int mt = 0; mt < 2; mt++) {
            const int m = wm * 32 + mt * 16 + gid;
            o0[m]     = acc[mt][nt][0] + b0;
            o1[m]     = acc[mt][nt][1] + b1;
            o0[m + 8] = acc[mt][nt][2] + b0;
            o1[m + 8] = acc[mt][nt][3] + b1;
        }
    }
}

extern "C" void kernel_launch(void* const* d_in, const int* in_sizes, int n_in,
                              void* d_out, int out_size) {
    const float* x = (const float*)d_in[0];   // [256,512,512]
    const float* w = (const float*)d_in[1];   // [3,3,256,256]
    const float* b = (const float*)d_in[2];   // [256]
    float* out = (float*)d_out;               // [256,512,512]

    prep_x<<<(256 * HWSZ / 4) / 256, 256>>>(reinterpret_cast<const float4*>(x));
    prep_w<<<(9 * 256 * 256) / 256, 256>>>(w);

    cudaFuncSetAttribute(conv_mma, cudaFuncAttributeMaxDynamicSharedMemorySize, SMEM_BYTES);
    dim3 grid(4, HH, 2);   // 4 w-tiles x 512 rows x 2 cout halves
    conv_mma<<<grid, 256, SMEM_BYTES>>>(b, out);
}

// round 5
// speedup vs baseline: 1.4525x; 1.4525x over previous
#include <cuda_runtime.h>
#include <cstdint>

// 3x3 conv s1 p1, implicit GEMM on mma.sync m16n8k8 tf32 (sm_103 baseline PTX).
// R5: R3 structure + tf32 prepass (no cvt in hot loop). A tile k-major
// (coalesced producer, scalar conflict-free LDS); B tile n-major stride-40
// with k-interleave (prepacked -> coalesced producer, LDS.64 conflict-free).

#define HH 512
#define WW 512
#define HWSZ (512*512)
#define C_OUT 256
#define NCHUNK 72
#define AKSTRIDE 136                        // A: floats per k-row
#define ATILE_BYTES (32 * AKSTRIDE * 4)     // 17408
#define BNSTRIDE 40                         // B: floats per n-row
#define BTILE_BYTES (128 * BNSTRIDE * 4)    // 20480
#define STAGE_BYTES (ATILE_BYTES + BTILE_BYTES)   // 37888
#define SMEM_BYTES (2 * STAGE_BYTES)              // 75776

// tf32 scratch (bss, not allocations)
__device__ uint32_t g_x[256 * HWSZ];
__device__ uint32_t g_w[9 * 256 * 256];   // [k9][cic(8)][coh(2)][n(128)][k32 interleaved]

__device__ __forceinline__ uint32_t to_tf32(float f) {
    uint32_t r;
    asm("cvt.rna.tf32.f32 %0, %1;" : "=r"(r) : "f"(f));
    return r;
}
__device__ __forceinline__ void cp_async4(uint32_t dst, const void* src, uint32_t sz) {
    asm volatile("cp.async.ca.shared.global [%0], [%1], 4, %2;"
                 :: "r"(dst), "l"(src), "r"(sz) : "memory");
}
__device__ __forceinline__ void cp_async16(uint32_t dst, const void* src) {
    asm volatile("cp.async.cg.shared.global [%0], [%1], 16;"
                 :: "r"(dst), "l"(src) : "memory");
}
__device__ __forceinline__ void cp_commit() {
    asm volatile("cp.async.commit_group;" ::: "memory");
}
__device__ __forceinline__ void cp_wait1() {
    asm volatile("cp.async.wait_group 1;" ::: "memory");
}
__device__ __forceinline__ void lds64(uint32_t& a, uint32_t& b, uint32_t addr) {
    asm volatile("ld.shared.v2.b32 {%0,%1}, [%2];" : "=r"(a), "=r"(b) : "r"(addr));
}
__device__ __forceinline__ uint32_t lds32(uint32_t addr) {
    uint32_t v;
    asm volatile("ld.shared.b32 %0, [%1];" : "=r"(v) : "r"(addr));
    return v;
}
__device__ __forceinline__ void mma_tf32(float* c, const uint32_t* a, const uint32_t* b) {
    asm volatile(
        "mma.sync.aligned.m16n8k8.row.col.f32.tf32.tf32.f32 "
        "{%0,%1,%2,%3}, {%4,%5,%6,%7}, {%8,%9}, {%0,%1,%2,%3};"
        : "+f"(c[0]), "+f"(c[1]), "+f"(c[2]), "+f"(c[3])
        : "r"(a[0]), "r"(a[1]), "r"(a[2]), "r"(a[3]), "r"(b[0]), "r"(b[1]));
}

// interleave within a 32-k group so logical (k, k+4) are physically adjacent
__device__ __forceinline__ int physk(int k) {
    return (k & 24) + ((k & 3) << 1) + ((k >> 2) & 1);
}

// ---------------- prepasses ----------------
__global__ void prep_x(const float4* __restrict__ x) {
    const int i = blockIdx.x * 256 + threadIdx.x;   // 16777216 float4s
    const float4 v = x[i];
    uint4 o;
    o.x = to_tf32(v.x); o.y = to_tf32(v.y); o.z = to_tf32(v.z); o.w = to_tf32(v.w);
    reinterpret_cast<uint4*>(g_x)[i] = o;
}
__global__ void prep_w(const float* __restrict__ w) {
    const int idx = blockIdx.x * 256 + threadIdx.x;  // 589824
    const int co = idx & 255;
    const int ci = (idx >> 8) & 255;
    const int k9 = idx >> 16;
    const int dst = (((k9 * 8 + (ci >> 5)) * 2 + (co >> 7)) << 12) +
                    ((co & 127) << 5) + physk(ci & 31);
    g_w[dst] = to_tf32(w[idx]);
}

// ---------------- main kernel ----------------
__global__ void __launch_bounds__(256, 2)
conv_mma(const float* __restrict__ bias, float* __restrict__ out)
{
    extern __shared__ uint32_t dsm[];

    const int tid  = threadIdx.x;
    const int wid  = tid >> 5;
    const int lane = tid & 31;
    const int gid  = lane >> 2;     // 0..7
    const int tig  = lane & 3;      // 0..3
    const int wm   = wid & 3;       // warp m-offset: 32*wm
    const int wn   = wid >> 2;      // warp n-offset: 64*wn

    const int w0  = blockIdx.x * 128;
    const int h   = blockIdx.y;
    const int coh = blockIdx.z;
    const int co0 = coh * 128;

    const uint32_t sbase = (uint32_t)__cvta_generic_to_shared(dsm);

    float acc[2][8][4];
#pragma unroll
    for (int mt = 0; mt < 2; mt++)
#pragma unroll
        for (int nt = 0; nt < 8; nt++)
#pragma unroll
            for (int i = 0; i < 4; i++)
                acc[mt][nt][i] = 0.f;

    auto load_chunk = [&](int c, int stage) {
        const int kh  = c / 24;
        const int r   = c % 24;
        const int kw  = r >> 3;
        const int cic = r & 7;
        const int ci0 = cic * 32;

        const uint32_t abase = sbase + (uint32_t)stage * STAGE_BYTES;
        const uint32_t bbase = abase + ATILE_BYTES;

        const int h2  = h + kh - 1;
        const bool hok = (unsigned)h2 < (unsigned)HH;
        const uint32_t* xrow = g_x + (size_t)ci0 * HWSZ + (size_t)(hok ? h2 : 0) * WW;

        // A: im2col tile [k=32][m=128] (k-major, coalesced), 16 scalars/thread
#pragma unroll
        for (int i = 0; i < 16; i++) {
            const int j = tid + i * 256;
            const int k = j >> 7, m = j & 127;
            const int w2 = w0 + m + kw - 1;
            const bool ok = hok && ((unsigned)w2 < (unsigned)WW);
            const uint32_t* src = xrow + (size_t)k * HWSZ + (ok ? w2 : 0);
            cp_async4(abase + (uint32_t)(k * AKSTRIDE + m) * 4u, src, ok ? 4u : 0u);
        }
        // B: pre-packed [n=128][k=32 interleaved] -> n-major stride 40
        const uint32_t* wb = g_w + ((((size_t)(kh * 3 + kw)) * 8 + cic) * 2 + coh) * 4096;
#pragma unroll
        for (int i = 0; i < 4; i++) {
            const int j = tid + i * 256;
            const int n = j >> 3, q = (j & 7) * 4;
            cp_async16(bbase + (uint32_t)(n * BNSTRIDE + q) * 4u, wb + n * 32 + q);
        }
    };

    load_chunk(0, 0); cp_commit();
    load_chunk(1, 1); cp_commit();

    // per-thread frag base offsets
    const uint32_t am0 = (uint32_t)(wm * 32 + gid);           // A m index
    const uint32_t boff = (uint32_t)((wn * 64 + gid) * BNSTRIDE + tig * 2) * 4u;

    for (int c = 0; c < NCHUNK; c++) {
        cp_wait1();
        __syncthreads();

        const uint32_t sA = sbase + (uint32_t)(c & 1) * STAGE_BYTES;
        const uint32_t sB = sA + ATILE_BYTES;

#pragma unroll
        for (int ks = 0; ks < 4; ks++) {
            const int kb = ks * 8 + tig;
            uint32_t afrag[2][4];
#pragma unroll
            for (int mt = 0; mt < 2; mt++) {
                const uint32_t a0 =
                    sA + (uint32_t)(kb * AKSTRIDE + am0 + mt * 16) * 4u;
                afrag[mt][0] = lds32(a0);
                afrag[mt][1] = lds32(a0 + 8 * 4u);
                afrag[mt][2] = lds32(a0 + (uint32_t)(4 * AKSTRIDE) * 4u);
                afrag[mt][3] = lds32(a0 + (uint32_t)(4 * AKSTRIDE + 8) * 4u);
            }
            uint32_t bfrag[8][2];
#pragma unroll
            for (int nt = 0; nt < 8; nt++) {
                lds64(bfrag[nt][0], bfrag[nt][1],
                      sB + boff + (uint32_t)(ks * 8) * 4u +
                      (uint32_t)(nt * 8 * BNSTRIDE) * 4u);
            }
#pragma unroll
            for (int mt = 0; mt < 2; mt++)
#pragma unroll
                for (int nt = 0; nt < 8; nt++)
                    mma_tf32(acc[mt][nt], afrag[mt], bfrag[nt]);
        }

        __syncthreads();
        if (c + 2 < NCHUNK) load_chunk(c + 2, c & 1);
        cp_commit();
    }

    // ---- epilogue: bias + store ----
    const size_t prow = (size_t)h * WW + w0;
#pragma unroll
    for (int nt = 0; nt < 8; nt++) {
        const int co = co0 + wn * 64 + nt * 8 + tig * 2;
        const float b0 = __ldg(bias + co);
        const float b1 = __ldg(bias + co + 1);
        float* o0 = out + (size_t)co * HWSZ + prow;
        float* o1 = o0 + HWSZ;
#pragma unroll
        for (int mt = 0; mt < 2; mt++) {
            const int m = wm * 32 + mt * 16 + gid;
            o0[m]     = acc[mt][nt][0] + b0;
            o1[m]     = acc[mt][nt][1] + b1;
            o0[m + 8] = acc[mt][nt][2] + b0;
            o1[m + 8] = acc[mt][nt][3] + b1;
        }
    }
}

extern "C" void kernel_launch(void* const* d_in, const int* in_sizes, int n_in,
                              void* d_out, int out_size) {
    const float* x = (const float*)d_in[0];   // [256,512,512]
    const float* w = (const float*)d_in[1];   // [3,3,256,256]
    const float* b = (const float*)d_in[2];   // [256]
    float* out = (float*)d_out;               // [256,512,512]

    prep_x<<<(256 * HWSZ / 4) / 256, 256>>>(reinterpret_cast<const float4*>(x));
    prep_w<<<(9 * 256 * 256) / 256, 256>>>(w);

    cudaFuncSetAttribute(conv_mma, cudaFuncAttributeMaxDynamicSharedMemorySize, SMEM_BYTES);
    dim3 grid(4, HH, 2);   // 4 w-tiles x 512 rows x 2 cout halves
    conv_mma<<<grid, 256, SMEM_BYTES>>>(b, out);
}

// round 6
// speedup vs baseline: 1.6086x; 1.1075x over previous
#include <cuda_runtime.h>
#include <cstdint>

// 3x3 conv s1 p1, implicit GEMM on mma.sync m16n8k8 tf32 (sm_103 baseline PTX).
// R6: A im2col tile widened to 132 cols and shared across the 3 kw chunks
// (consumer applies a kw-column shift); chunk order (kh, cic, kw-innermost).
// tf32 prepass keeps cvt out of the hot loop.

#define HH 512
#define WW 512
#define HWSZ (512*512)
#define C_OUT 256
#define NCHUNK 72
#define AKSTRIDE 136                        // A: floats per k-row (132 used)
#define ATILE_BYTES (32 * AKSTRIDE * 4)     // 17408
#define BNSTRIDE 40                         // B: floats per n-row
#define BTILE_BYTES (128 * BNSTRIDE * 4)    // 20480
#define A_OFF 0
#define B_OFF (2 * ATILE_BYTES)             // A stages first, then B stages
#define SMEM_BYTES (2 * ATILE_BYTES + 2 * BTILE_BYTES)   // 75776

// tf32 scratch (bss, not allocations)
__device__ uint32_t g_x[256 * HWSZ];
__device__ uint32_t g_w[9 * 256 * 256];   // [k9][cic(8)][coh(2)][n(128)][k32 interleaved]

__device__ __forceinline__ uint32_t to_tf32(float f) {
    uint32_t r;
    asm("cvt.rna.tf32.f32 %0, %1;" : "=r"(r) : "f"(f));
    return r;
}
__device__ __forceinline__ void cp_async4(uint32_t dst, const void* src, uint32_t sz) {
    asm volatile("cp.async.ca.shared.global [%0], [%1], 4, %2;"
                 :: "r"(dst), "l"(src), "r"(sz) : "memory");
}
__device__ __forceinline__ void cp_async16(uint32_t dst, const void* src) {
    asm volatile("cp.async.cg.shared.global [%0], [%1], 16;"
                 :: "r"(dst), "l"(src) : "memory");
}
__device__ __forceinline__ void cp_commit() {
    asm volatile("cp.async.commit_group;" ::: "memory");
}
__device__ __forceinline__ void cp_wait1() {
    asm volatile("cp.async.wait_group 1;" ::: "memory");
}
__device__ __forceinline__ void lds64(uint32_t& a, uint32_t& b, uint32_t addr) {
    asm volatile("ld.shared.v2.b32 {%0,%1}, [%2];" : "=r"(a), "=r"(b) : "r"(addr));
}
__device__ __forceinline__ uint32_t lds32(uint32_t addr) {
    uint32_t v;
    asm volatile("ld.shared.b32 %0, [%1];" : "=r"(v) : "r"(addr));
    return v;
}
__device__ __forceinline__ void mma_tf32(float* c, const uint32_t* a, const uint32_t* b) {
    asm volatile(
        "mma.sync.aligned.m16n8k8.row.col.f32.tf32.tf32.f32 "
        "{%0,%1,%2,%3}, {%4,%5,%6,%7}, {%8,%9}, {%0,%1,%2,%3};"
        : "+f"(c[0]), "+f"(c[1]), "+f"(c[2]), "+f"(c[3])
        : "r"(a[0]), "r"(a[1]), "r"(a[2]), "r"(a[3]), "r"(b[0]), "r"(b[1]));
}

// interleave within a 32-k group so logical (k, k+4) are physically adjacent
__device__ __forceinline__ int physk(int k) {
    return (k & 24) + ((k & 3) << 1) + ((k >> 2) & 1);
}

// ---------------- prepasses ----------------
__global__ void prep_x(const float4* __restrict__ x) {
    const int i = blockIdx.x * 256 + threadIdx.x;   // 16777216 float4s
    const float4 v = x[i];
    uint4 o;
    o.x = to_tf32(v.x); o.y = to_tf32(v.y); o.z = to_tf32(v.z); o.w = to_tf32(v.w);
    reinterpret_cast<uint4*>(g_x)[i] = o;
}
__global__ void prep_w(const float* __restrict__ w) {
    const int idx = blockIdx.x * 256 + threadIdx.x;  // 589824
    const int co = idx & 255;
    const int ci = (idx >> 8) & 255;
    const int k9 = idx >> 16;
    const int dst = (((k9 * 8 + (ci >> 5)) * 2 + (co >> 7)) << 12) +
                    ((co & 127) << 5) + physk(ci & 31);
    g_w[dst] = to_tf32(w[idx]);
}

// ---------------- main kernel ----------------
__global__ void __launch_bounds__(256, 2)
conv_mma(const float* __restrict__ bias, float* __restrict__ out)
{
    extern __shared__ uint32_t dsm[];

    const int tid  = threadIdx.x;
    const int wid  = tid >> 5;
    const int lane = tid & 31;
    const int gid  = lane >> 2;     // 0..7
    const int tig  = lane & 3;      // 0..3
    const int wm   = wid & 3;       // warp m-offset: 32*wm
    const int wn   = wid >> 2;      // warp n-offset: 64*wn

    const int w0  = blockIdx.x * 128;
    const int h   = blockIdx.y;
    const int coh = blockIdx.z;
    const int co0 = coh * 128;

    const uint32_t sbase = (uint32_t)__cvta_generic_to_shared(dsm);

    float acc[2][8][4];
#pragma unroll
    for (int mt = 0; mt < 2; mt++)
#pragma unroll
        for (int nt = 0; nt < 8; nt++)
#pragma unroll
            for (int i = 0; i < 4; i++)
                acc[mt][nt][i] = 0.f;

    // A tile for at = kh*8 + cic: [k=32][col=132 used, stride 136],
    // col 0 = pixel w0-1.
    auto load_A = [&](int at, int stage) {
        const int kh  = at >> 3;
        const int ci0 = (at & 7) * 32;
        const uint32_t abase = sbase + A_OFF + (uint32_t)stage * ATILE_BYTES;

        const int h2  = h + kh - 1;
        const bool hok = (unsigned)h2 < (unsigned)HH;
        const uint32_t* xrow = g_x + (size_t)ci0 * HWSZ + (size_t)(hok ? h2 : 0) * WW;

#pragma unroll
        for (int i = 0; i < 17; i++) {              // 4352 = 32*136 tasks
            const int j = tid + i * 256;
            const int k = j / AKSTRIDE, col = j % AKSTRIDE;
            const int w2 = w0 + col - 1;
            const bool ok = hok && (col < 132) && ((unsigned)w2 < (unsigned)WW);
            const uint32_t* src = xrow + (size_t)k * HWSZ + (ok ? w2 : 0);
            cp_async4(abase + (uint32_t)j * 4u, src, ok ? 4u : 0u);
        }
    };
    // B tile for chunk c: (kh, cic, kw innermost)
    auto load_B = [&](int c, int stage) {
        const int kh  = c / 24;
        const int r   = c % 24;
        const int cic = r / 3;
        const int kw  = r % 3;
        const uint32_t bbase = sbase + B_OFF + (uint32_t)stage * BTILE_BYTES;
        const uint32_t* wb = g_w + ((((size_t)(kh * 3 + kw)) * 8 + cic) * 2 + coh) * 4096;
#pragma unroll
        for (int i = 0; i < 4; i++) {
            const int j = tid + i * 256;
            const int n = j >> 3, q = (j & 7) * 4;
            cp_async16(bbase + (uint32_t)(n * BNSTRIDE + q) * 4u, wb + n * 32 + q);
        }
    };

    load_A(0, 0); load_B(0, 0); cp_commit();       // group for chunk 0
    load_B(1, 1); cp_commit();                     // group for chunk 1 (same A)

    const uint32_t am0  = (uint32_t)(wm * 32 + gid);
    const uint32_t boff = (uint32_t)((wn * 64 + gid) * BNSTRIDE + tig * 2) * 4u;

    for (int c = 0; c < NCHUNK; c++) {
        cp_wait1();
        __syncthreads();

        const int kw = c % 3;
        // A base includes the kw column shift (pixel m reads col m+kw)
        const uint32_t sA = sbase + A_OFF +
                            (uint32_t)(((c / 3) & 1) ? ATILE_BYTES : 0) +
                            (uint32_t)kw * 4u;
        const uint32_t sB = sbase + B_OFF + (uint32_t)((c & 1) ? BTILE_BYTES : 0);

#pragma unroll
        for (int ks = 0; ks < 4; ks++) {
            const int kb = ks * 8 + tig;
            uint32_t afrag[2][4];
#pragma unroll
            for (int mt = 0; mt < 2; mt++) {
                const uint32_t a0 =
                    sA + (uint32_t)(kb * AKSTRIDE + am0 + mt * 16) * 4u;
                afrag[mt][0] = lds32(a0);
                afrag[mt][1] = lds32(a0 + 8 * 4u);
                afrag[mt][2] = lds32(a0 + (uint32_t)(4 * AKSTRIDE) * 4u);
                afrag[mt][3] = lds32(a0 + (uint32_t)(4 * AKSTRIDE + 8) * 4u);
            }
            uint32_t bfrag[8][2];
#pragma unroll
            for (int nt = 0; nt < 8; nt++) {
                lds64(bfrag[nt][0], bfrag[nt][1],
                      sB + boff + (uint32_t)(ks * 8) * 4u +
                      (uint32_t)(nt * 8 * BNSTRIDE) * 4u);
            }
#pragma unroll
            for (int mt = 0; mt < 2; mt++)
#pragma unroll
                for (int nt = 0; nt < 8; nt++)
                    mma_tf32(acc[mt][nt], afrag[mt], bfrag[nt]);
        }

        __syncthreads();
        const int cn = c + 2;
        if (cn < NCHUNK) {
            if (cn % 3 == 0) load_A(cn / 3, (cn / 3) & 1);
            load_B(cn, cn & 1);
        }
        cp_commit();
    }

    // ---- epilogue: bias + store ----
    const size_t prow = (size_t)h * WW + w0;
#pragma unroll
    for (int nt = 0; nt < 8; nt++) {
        const int co = co0 + wn * 64 + nt * 8 + tig * 2;
        const float b0 = __ldg(bias + co);
        const float b1 = __ldg(bias + co + 1);
        float* o0 = out + (size_t)co * HWSZ + prow;
        float* o1 = o0 + HWSZ;
#pragma unroll
        for (int mt = 0; mt < 2; mt++) {
            const int m = wm * 32 + mt * 16 + gid;
            o0[m]     = acc[mt][nt][0] + b0;
            o1[m]     = acc[mt][nt][1] + b1;
            o0[m + 8] = acc[mt][nt][2] + b0;
            o1[m + 8] = acc[mt][nt][3] + b1;
        }
    }
}

extern "C" void kernel_launch(void* const* d_in, const int* in_sizes, int n_in,
                              void* d_out, int out_size) {
    const float* x = (const float*)d_in[0];   // [256,512,512]
    const float* w = (const float*)d_in[1];   // [3,3,256,256]
    const float* b = (const float*)d_in[2];   // [256]
    float* out = (float*)d_out;               // [256,512,512]

    prep_x<<<(256 * HWSZ / 4) / 256, 256>>>(reinterpret_cast<const float4*>(x));
    prep_w<<<(9 * 256 * 256) / 256, 256>>>(w);

    cudaFuncSetAttribute(conv_mma, cudaFuncAttributeMaxDynamicSharedMemorySize, SMEM_BYTES);
    dim3 grid(4, HH, 2);   // 4 w-tiles x 512 rows x 2 cout halves
    conv_mma<<<grid, 256, SMEM_BYTES>>>(b, out);
}

// round 7
// speedup vs baseline: 2.9006x; 1.8033x over previous
#include <cuda_runtime.h>
#include <cuda_fp16.h>
#include <cstdint>

// 3x3 conv s1 p1, implicit GEMM via mma.sync m16n8k16 fp16 (f32 accum).
// R7: fp16 halves MMA instr count, LDS bytes and tile bytes vs tf32 k8.
// x prepacked as ci-pair half2 (g_x2), W prepacked half2 + kp interleave (g_w).
// A im2col tile shared across 3 kw chunks via column shift (R6 trick).

#define HH 512
#define WW 512
#define HWSZ (512*512)
#define NCHUNK 72
#define AKSTRIDE 136                         // A: u32 (half2) per kp-row, 132 used
#define ATILE_BYTES (16 * AKSTRIDE * 4)      // 8704
#define BNSTRIDE 24                          // B: u32 per n-row (16 used)
#define BTILE_BYTES (128 * BNSTRIDE * 4)     // 12288
#define A_OFF 0
#define B_OFF (2 * ATILE_BYTES)
#define SMEM_BYTES (2 * ATILE_BYTES + 2 * BTILE_BYTES)   // 41984

// scratch (bss, not allocations)
__device__ uint32_t g_x2[128 * HWSZ];        // [cipair][pixel] = (ci even lo, ci odd hi)
__device__ uint32_t g_w[9 * 8 * 2 * 128 * 16]; // [k9][cic][coh][n][16 kp slots]

__device__ __forceinline__ uint32_t packh2(float lo, float hi) {
    uint32_t d;
    asm("cvt.rn.f16x2.f32 %0, %1, %2;" : "=r"(d) : "f"(hi), "f"(lo));
    return d;
}
__device__ __forceinline__ void cp_async4(uint32_t dst, const void* src, uint32_t sz) {
    asm volatile("cp.async.ca.shared.global [%0], [%1], 4, %2;"
                 :: "r"(dst), "l"(src), "r"(sz) : "memory");
}
__device__ __forceinline__ void cp_async16(uint32_t dst, const void* src) {
    asm volatile("cp.async.cg.shared.global [%0], [%1], 16;"
                 :: "r"(dst), "l"(src) : "memory");
}
__device__ __forceinline__ void cp_commit() {
    asm volatile("cp.async.commit_group;" ::: "memory");
}
__device__ __forceinline__ void cp_wait1() {
    asm volatile("cp.async.wait_group 1;" ::: "memory");
}
__device__ __forceinline__ void lds64(uint32_t& a, uint32_t& b, uint32_t addr) {
    asm volatile("ld.shared.v2.b32 {%0,%1}, [%2];" : "=r"(a), "=r"(b) : "r"(addr));
}
__device__ __forceinline__ uint32_t lds32(uint32_t addr) {
    uint32_t v;
    asm volatile("ld.shared.b32 %0, [%1];" : "=r"(v) : "r"(addr));
    return v;
}
__device__ __forceinline__ void mma_fp16(float* c, const uint32_t* a, const uint32_t* b) {
    asm volatile(
        "mma.sync.aligned.m16n8k16.row.col.f32.f16.f16.f32 "
        "{%0,%1,%2,%3}, {%4,%5,%6,%7}, {%8,%9}, {%0,%1,%2,%3};"
        : "+f"(c[0]), "+f"(c[1]), "+f"(c[2]), "+f"(c[3])
        : "r"(a[0]), "r"(a[1]), "r"(a[2]), "r"(a[3]), "r"(b[0]), "r"(b[1]));
}

// ---------------- prepasses ----------------
__global__ void prep_x(const float* __restrict__ x) {
    const int t = blockIdx.x * 256 + threadIdx.x;  // 128 cipairs * 65536
    const int c = t >> 16;
    const int p4 = (t & 65535) * 4;
    const float4 v0 = *reinterpret_cast<const float4*>(x + (size_t)(2 * c) * HWSZ + p4);
    const float4 v1 = *reinterpret_cast<const float4*>(x + (size_t)(2 * c + 1) * HWSZ + p4);
    uint4 o;
    o.x = packh2(v0.x, v1.x);
    o.y = packh2(v0.y, v1.y);
    o.z = packh2(v0.z, v1.z);
    o.w = packh2(v0.w, v1.w);
    reinterpret_cast<uint4*>(g_x2)[(size_t)c * 65536 + (t & 65535)] = o;
}
__global__ void prep_w(const float* __restrict__ w) {
    const int t = blockIdx.x * 256 + threadIdx.x;  // 294912
    const int kp  = t & 15;
    const int n   = (t >> 4) & 127;
    const int coh = (t >> 11) & 1;
    const int cic = (t >> 12) & 7;
    const int k9  = t >> 15;
    const int ci = cic * 32 + kp * 2;
    const int co = coh * 128 + n;
    const float lo = w[((size_t)k9 * 256 + ci) * 256 + co];
    const float hi = w[((size_t)k9 * 256 + ci + 1) * 256 + co];
    // slot interleave: logical kp -> phys so (tig, tig+4) within 8-group are adjacent
    const int phys = (kp & 8) + ((kp & 3) << 1) + ((kp >> 2) & 1);
    g_w[(((size_t)(k9 * 8 + cic)) * 2 + coh) * 2048 + n * 16 + phys] = packh2(lo, hi);
}

// ---------------- main kernel ----------------
__global__ void __launch_bounds__(256, 2)
conv_mma(const float* __restrict__ bias, float* __restrict__ out)
{
    extern __shared__ uint32_t dsm[];

    const int tid  = threadIdx.x;
    const int wid  = tid >> 5;
    const int lane = tid & 31;
    const int gid  = lane >> 2;
    const int tig  = lane & 3;
    const int wm   = wid & 3;      // warp m-offset: 32*wm
    const int wn   = wid >> 2;     // warp n-offset: 64*wn

    const int w0  = blockIdx.x * 128;
    const int h   = blockIdx.y;
    const int coh = blockIdx.z;
    const int co0 = coh * 128;

    const uint32_t sbase = (uint32_t)__cvta_generic_to_shared(dsm);

    float acc[2][8][4];
#pragma unroll
    for (int mt = 0; mt < 2; mt++)
#pragma unroll
        for (int nt = 0; nt < 8; nt++)
#pragma unroll
            for (int i = 0; i < 4; i++)
                acc[mt][nt][i] = 0.f;

    // A tile for at = kh*8 + cic: [kp=16][col=132 used, stride 136] of half2,
    // col 0 = pixel w0-1.
    auto load_A = [&](int at, int stage) {
        const int kh = at >> 3;
        const int cp0 = (at & 7) * 16;       // cipair base
        const uint32_t abase = sbase + A_OFF + (uint32_t)stage * ATILE_BYTES;

        const int h2 = h + kh - 1;
        const bool hok = (unsigned)h2 < (unsigned)HH;
        const uint32_t* xrow = g_x2 + (size_t)cp0 * HWSZ + (size_t)(hok ? h2 : 0) * WW;

#pragma unroll
        for (int i = 0; i < 9; i++) {        // 2176 = 16*136 tasks
            const int j = tid + i * 256;
            if (j < 2176) {
                const int kp = j / AKSTRIDE, col = j % AKSTRIDE;
                const int w2 = w0 + col - 1;
                const bool ok = hok && (col < 132) && ((unsigned)w2 < (unsigned)WW);
                const uint32_t* src = xrow + (size_t)kp * HWSZ + (ok ? w2 : 0);
                cp_async4(abase + (uint32_t)j * 4u, src, ok ? 4u : 0u);
            }
        }
    };
    // B tile for chunk c (kh, cic, kw innermost): contiguous 512 float4 copy
    auto load_B = [&](int c, int stage) {
        const int kh  = c / 24;
        const int r   = c % 24;
        const int cic = r / 3;
        const int kw  = r % 3;
        const uint32_t bbase = sbase + B_OFF + (uint32_t)stage * BTILE_BYTES;
        const uint32_t* wb = g_w + (((size_t)((kh * 3 + kw) * 8 + cic)) * 2 + coh) * 2048;
#pragma unroll
        for (int i = 0; i < 2; i++) {
            const int j = tid + i * 256;     // 512 float4s
            const int n = j >> 2, q = j & 3;
            cp_async16(bbase + (uint32_t)(n * BNSTRIDE + q * 4) * 4u, wb + j * 4);
        }
    };

    load_A(0, 0); load_B(0, 0); cp_commit();
    load_B(1, 1); cp_commit();

    const uint32_t am0  = (uint32_t)(wm * 32 + gid);
    const uint32_t boff = (uint32_t)((wn * 64 + gid) * BNSTRIDE + tig * 2) * 4u;

    for (int c = 0; c < NCHUNK; c++) {
        cp_wait1();
        __syncthreads();

        const int kw = c % 3;
        const uint32_t sA = sbase + A_OFF +
                            (uint32_t)(((c / 3) & 1) ? ATILE_BYTES : 0) +
                            (uint32_t)kw * 4u;          // kw column shift
        const uint32_t sB = sbase + B_OFF + (uint32_t)((c & 1) ? BTILE_BYTES : 0);

#pragma unroll
        for (int ks = 0; ks < 2; ks++) {
            const int kp = ks * 8 + tig;
            uint32_t afrag[2][4];
#pragma unroll
            for (int mt = 0; mt < 2; mt++) {
                const uint32_t a0 = sA + (uint32_t)(kp * AKSTRIDE + am0 + mt * 16) * 4u;
                afrag[mt][0] = lds32(a0);
                afrag[mt][1] = lds32(a0 + 8 * 4u);
                afrag[mt][2] = lds32(a0 + (uint32_t)(4 * AKSTRIDE) * 4u);
                afrag[mt][3] = lds32(a0 + (uint32_t)(4 * AKSTRIDE + 8) * 4u);
            }
            uint32_t bfrag[8][2];
#pragma unroll
            for (int nt = 0; nt < 8; nt++) {
                lds64(bfrag[nt][0], bfrag[nt][1],
                      sB + boff + (uint32_t)(ks * 8) * 4u +
                      (uint32_t)(nt * 8 * BNSTRIDE) * 4u);
            }
#pragma unroll
            for (int mt = 0; mt < 2; mt++)
#pragma unroll
                for (int nt = 0; nt < 8; nt++)
                    mma_fp16(acc[mt][nt], afrag[mt], bfrag[nt]);
        }

        __syncthreads();
        const int cn = c + 2;
        if (cn < NCHUNK) {
            if (cn % 3 == 0) load_A(cn / 3, (cn / 3) & 1);
            load_B(cn, cn & 1);
        }
        cp_commit();
    }

    // ---- epilogue: bias + store ----
    const size_t prow = (size_t)h * WW + w0;
#pragma unroll
    for (int nt = 0; nt < 8; nt++) {
        const int co = co0 + wn * 64 + nt * 8 + tig * 2;
        const float b0 = __ldg(bias + co);
        const float b1 = __ldg(bias + co + 1);
        float* o0 = out + (size_t)co * HWSZ + prow;
        float* o1 = o0 + HWSZ;
#pragma unroll
        for (int mt = 0; mt < 2; mt++) {
            const int m = wm * 32 + mt * 16 + gid;
            o0[m]     = acc[mt][nt][0] + b0;
            o1[m]     = acc[mt][nt][1] + b1;
            o0[m + 8] = acc[mt][nt][2] + b0;
            o1[m + 8] = acc[mt][nt][3] + b1;
        }
    }
}

extern "C" void kernel_launch(void* const* d_in, const int* in_sizes, int n_in,
                              void* d_out, int out_size) {
    const float* x = (const float*)d_in[0];   // [256,512,512]
    const float* w = (const float*)d_in[1];   // [3,3,256,256]
    const float* b = (const float*)d_in[2];   // [256]
    float* out = (float*)d_out;               // [256,512,512]

    prep_x<<<(128 * (HWSZ / 4)) / 256, 256>>>(x);
    prep_w<<<(9 * 8 * 2 * 128 * 16) / 256, 256>>>(w);

    cudaFuncSetAttribute(conv_mma, cudaFuncAttributeMaxDynamicSharedMemorySize, SMEM_BYTES);
    dim3 grid(4, HH, 2);   // 4 w-tiles x 512 rows x 2 cout halves
    conv_mma<<<grid, 256, SMEM_BYTES>>>(b, out);
}